// round 2
// baseline (speedup 1.0000x reference)
#include <cuda_runtime.h>
#include <math.h>

// Problem constants (fixed by the dataset)
constexpr int H_   = 768;
constexpr int NC_  = 8;       // chunks
constexpr int NL_  = 8921;    // labels
constexpr int NN_  = 4;       // notes
constexpr int JB_  = 1115;    // lw bucket width: bucket(j) = min(j/1115, 7); 8921 = 8*1115+1
// Segmentation of the two streaming reductions
constexpr int ESEG  = 16;     // segments per encoding chunk
constexpr int EROWS = 32;     // 16*32 = 512 rows per chunk
constexpr int LSEG  = 32;     // segments per lw bucket
constexpr int LROWS = 35;     // 32*35 = 1120 >= 1116 (last bucket)
constexpr int HG    = 3;      // 768 / 256 column groups
constexpr int ENC_BLOCKS = NC_ * ESEG * HG;   // 384
constexpr int LW_BLOCKS  = NC_ * LSEG * HG;   // 768

// Scratch: partial sums (fully overwritten every call -> no zeroing, graph-safe)
__device__ float g_pe[NC_ * ESEG * H_];   // encoding partials
__device__ float g_pl[NC_ * LSEG * H_];   // label_weights partials

// Kernel 1: streaming column-wise block sums of encoding and label_weights.
// Warp lanes read consecutive h -> fully coalesced 128B transactions.
__global__ __launch_bounds__(256) void part_kernel(const float* __restrict__ enc,
                                                   const float* __restrict__ lw) {
    int b   = blockIdx.x;
    int tid = threadIdx.x;
    if (b < ENC_BLOCKS) {
        int hg = b % HG;
        int s  = (b / HG) % ESEG;
        int c  = b / (HG * ESEG);
        int h  = hg * 256 + tid;
        const float* p = enc + (size_t)(c * 512 + s * EROWS) * H_ + h;
        float a0 = 0.f, a1 = 0.f, a2 = 0.f, a3 = 0.f;
        #pragma unroll
        for (int r = 0; r < EROWS; r += 4) {
            a0 += p[(r + 0) * H_];
            a1 += p[(r + 1) * H_];
            a2 += p[(r + 2) * H_];
            a3 += p[(r + 3) * H_];
        }
        g_pe[(c * ESEG + s) * H_ + h] = (a0 + a1) + (a2 + a3);
    } else {
        b -= ENC_BLOCKS;
        int hg = b % HG;
        int s  = (b / HG) % LSEG;
        int c  = b / (HG * LSEG);
        int h  = hg * 256 + tid;
        int r0   = c * JB_ + s * LROWS;
        int rend = min(r0 + LROWS, (c == NC_ - 1) ? NL_ : (c + 1) * JB_);
        float a0 = 0.f, a1 = 0.f, a2 = 0.f, a3 = 0.f;
        int r = r0;
        for (; r + 4 <= rend; r += 4) {
            a0 += lw[(size_t)(r + 0) * H_ + h];
            a1 += lw[(size_t)(r + 1) * H_ + h];
            a2 += lw[(size_t)(r + 2) * H_ + h];
            a3 += lw[(size_t)(r + 3) * H_ + h];
        }
        float tail = 0.f;
        for (; r < rend; ++r) tail += lw[(size_t)r * H_ + h];
        g_pl[(c * LSEG + s) * H_ + h] = ((a0 + a1) + (a2 + a3)) + tail;
    }
}

// Kernel 2: reduce partials, build the (4x8) softmax weight table from note ids,
// apply chunk-boundary corrections, sigmoid, write output (4 x 768).
__global__ __launch_bounds__(256) void final_kernel(const float* __restrict__ lw,
                                                    const void* __restrict__ idsRaw,
                                                    float* __restrict__ out) {
    __shared__ float sCS[NC_][32];   // per-chunk encoding column sums
    __shared__ float sL[NC_][32];    // per-bucket lw column sums
    int tid = threadIdx.x;
    {
        int c  = tid >> 5;           // 0..7
        int hl = tid & 31;
        int h  = blockIdx.x * 32 + hl;
        float se = 0.f;
        #pragma unroll
        for (int s = 0; s < ESEG; ++s) se += g_pe[(c * ESEG + s) * H_ + h];
        float sl = 0.f;
        #pragma unroll
        for (int s = 0; s < LSEG; ++s) sl += g_pl[(c * LSEG + s) * H_ + h];
        sCS[c][hl] = se;
        sL[c][hl]  = sl;
    }
    __syncthreads();

    if (tid < 32 * NN_) {
        int n  = tid >> 5;           // note 0..3
        int hl = tid & 31;
        int h  = blockIdx.x * 32 + hl;

        // ---- load note_end_chunk_ids; detect int64 vs int32 layout ----
        const int* w = (const int*)idsRaw;
        int ids[NN_];
        bool is64 = true;
        int v[NN_];
        #pragma unroll
        for (int i = 0; i < NN_; ++i) {
            int lo = w[2 * i], hi = w[2 * i + 1];
            v[i] = lo;
            if (hi != 0 || lo < 0 || lo >= NC_) is64 = false;
        }
        #pragma unroll
        for (int i = 0; i + 1 < NN_; ++i)
            if (v[i] > v[i + 1]) is64 = false;
        #pragma unroll
        for (int i = 0; i < NN_; ++i) ids[i] = is64 ? v[i] : w[i];

        // ---- softmax weight table row for this note ----
        // masked(n, chunk c) <=> c <= ids[n]; unmasked count = #{i : ids[i] < c}
        float Wn[NC_];
        #pragma unroll
        for (int c = 0; c < NC_; ++c) {
            int cnt = 0;
            #pragma unroll
            for (int i = 0; i < NN_; ++i) cnt += (ids[i] < c) ? 1 : 0;
            bool un = (ids[n] < c);
            Wn[c] = (cnt > 0) ? (un ? 1.0f / (float)cnt : 0.0f) : 0.25f;
        }

        // ---- main term: Ptot * sum_c Wn[c] * L[c,h] ----
        float Ptot = 0.f, dot = 0.f;
        #pragma unroll
        for (int c = 0; c < NC_; ++c) {
            Ptot += sCS[c][hl];
            dot  += Wn[c] * sL[c][hl];
        }
        float score = Ptot * dot;

        // ---- boundary corrections: j = 1115k straddles chunks (k-1, k) at qs = 512k ----
        float P = 0.f;
        #pragma unroll
        for (int k = 1; k < NC_; ++k) {
            P += sCS[k - 1][hl];              // P[512k, h] prefix
            float wd = Wn[k - 1] - Wn[k];
            if (wd != 0.0f)
                score += wd * lw[(size_t)(JB_ * k) * H_ + h] * P;
        }

        out[n * H_ + h] = 1.0f / (1.0f + expf(-score));
    }
}

extern "C" void kernel_launch(void* const* d_in, const int* in_sizes, int n_in,
                              void* d_out, int out_size) {
    const float* enc = (const float*)d_in[0];   // encoding (4096, 768)
    // d_in[1] = label_queries: provably unused (softmax over note axis cancels scores)
    const float* lw  = (const float*)d_in[2];   // label_weights flat (768*8921)
    const void*  ids = d_in[3];                 // note_end_chunk_ids (4, int32 or int64)
    float* out = (float*)d_out;                 // (4, 768) float32

    part_kernel<<<ENC_BLOCKS + LW_BLOCKS, 256>>>(enc, lw);
    final_kernel<<<H_ / 32, 256>>>(lw, ids, out);
}